// round 9
// baseline (speedup 1.0000x reference)
#include <cuda_runtime.h>
#include <cstdint>

#define N_  4096
#define D_  128
#define R_  256
#define O_  64

typedef unsigned long long ull;

// ---------------- scratch (__device__ globals) -------------------------------
__device__ float g_w4[D_ * R_];
__device__ float g_u4[D_ * R_];
__device__ float g_k[R_];
__device__ float g_norm[(size_t)N_ * R_];              // [n][r]
__device__ __align__(16) ull g_Bh[(size_t)R_ * 2048];  // bf16 B frags [r][half2][kk4][jt8][lane32]
__device__ __align__(16) ull g_Bbh[8 * 512];           // bf16 bias frags [sp][kk2][jt8][lane32]
__device__ float g_partial[8][(size_t)N_ * O_];

// ---------------- helpers ----------------------------------------------------
__device__ __forceinline__ ull pack2(float lo, float hi) {
    ull r; asm("mov.b64 %0, {%1, %2};" : "=l"(r) : "f"(lo), "f"(hi)); return r;
}
__device__ __forceinline__ void unpack2(ull v, float& lo, float& hi) {
    asm("mov.b64 {%0, %1}, %2;" : "=f"(lo), "=f"(hi) : "l"(v));
}
__device__ __forceinline__ ull fma2(ull a, ull b, ull c) {
    ull d; asm("fma.rn.f32x2 %0, %1, %2, %3;" : "=l"(d) : "l"(a), "l"(b), "l"(c)); return d;
}
__device__ __forceinline__ uint32_t bf2(float a, float b) {   // lo=a, hi=b
    uint32_t r; asm("cvt.rn.bf16x2.f32 %0, %1, %2;" : "=r"(r) : "f"(b), "f"(a)); return r;
}
__device__ __forceinline__ uint32_t hmul2(uint32_t a, uint32_t b) {
    uint32_t r; asm("mul.bf16x2 %0, %1, %2;" : "=r"(r) : "r"(a), "r"(b)); return r;
}
__device__ __forceinline__ void u64lohi(ull v, uint32_t& lo, uint32_t& hi) {
    asm("mov.b64 {%0, %1}, %2;" : "=r"(lo), "=r"(hi) : "l"(v));
}
__device__ __forceinline__ uint32_t smem_u32(const void* p) {
    uint32_t a;
    asm("{ .reg .u64 t; cvta.to.shared.u64 t, %1; cvt.u32.u64 %0, t; }" : "=r"(a) : "l"(p));
    return a;
}
__device__ __forceinline__ void mma_bf16(float* c,
                                         uint32_t a0, uint32_t a1, uint32_t a2, uint32_t a3,
                                         uint32_t b0, uint32_t b1) {
    asm volatile(
        "mma.sync.aligned.m16n8k16.row.col.f32.bf16.bf16.f32 "
        "{%0,%1,%2,%3}, {%4,%5,%6,%7}, {%8,%9}, {%0,%1,%2,%3};"
        : "+f"(c[0]), "+f"(c[1]), "+f"(c[2]), "+f"(c[3])
        : "r"(a0), "r"(a1), "r"(a2), "r"(a3), "r"(b0), "r"(b1));
}

// ---------------------------------------------------------------------------
// Kernel 1: membership params -> quad layout
// ---------------------------------------------------------------------------
__global__ void prep_kernel(const float* __restrict__ centers,
                            const float* __restrict__ sigmas) {
    int r = blockIdx.x, d = threadIdx.x;
    float c  = centers[r * D_ + d];
    float sg = sigmas [r * D_ + d];
    float inv = 1.0f / (sg * sg);
    float w = 0.5f * inv;
    float u = c * inv;
    int q = (d >> 2) * (R_ * 4) + r * 4 + (d & 3);
    g_w4[q] = w;
    g_u4[q] = u;
    __shared__ float red[128];
    red[d] = w * c * c;
    __syncthreads();
    for (int s = 64; s > 0; s >>= 1) { if (d < s) red[d] += red[d + s]; __syncthreads(); }
    if (d == 0) g_k[r] = red[0];
}

// ---------------------------------------------------------------------------
// Kernel 2: strengths + normalization. 512 blocks x 256 thr, 8 rows/block.
// ---------------------------------------------------------------------------
#define XSTR 10
__global__ void __launch_bounds__(256) strengths_kernel(const float* __restrict__ X) {
    __shared__ float Xs[128 * XSTR];
    __shared__ float Wsum[8][8];
    __shared__ float Sinv[8];

    const int tid = threadIdx.x;
    const int nb  = blockIdx.x * 8;
    const int lane = tid & 31, wp = tid >> 5;

    for (int idx = tid; idx < 8 * 128; idx += 256) {
        int n = idx >> 7, d = idx & 127;
        Xs[d * XSTR + n] = X[(size_t)(nb + n) * D_ + d];
    }
    __syncthreads();

    const int r = tid;
    float kk = g_k[r];
    ull s[4];
    ull init = pack2(-kk, -kk);
    #pragma unroll
    for (int p = 0; p < 4; ++p) s[p] = init;

    #pragma unroll 4
    for (int c = 0; c < 32; ++c) {
        float4 w4 = *(const float4*)&g_w4[(c * R_ + r) * 4];
        float4 u4 = *(const float4*)&g_u4[(c * R_ + r) * 4];
        const float wv[4] = {w4.x, w4.y, w4.z, w4.w};
        const float uv[4] = {u4.x, u4.y, u4.z, u4.w};
        #pragma unroll
        for (int dd = 0; dd < 4; ++dd) {
            ull w2 = pack2(-wv[dd], -wv[dd]);
            ull u2 = pack2(uv[dd], uv[dd]);
            const float* xrow = &Xs[(c * 4 + dd) * XSTR];
            #pragma unroll
            for (int p = 0; p < 4; ++p) {
                ull xp = *(const ull*)&xrow[p * 2];
                ull t  = fma2(w2, xp, u2);
                s[p]   = fma2(t, xp, s[p]);
            }
        }
    }

    float e[8];
    #pragma unroll
    for (int p = 0; p < 4; ++p) {
        float a, b;
        unpack2(s[p], a, b);
        e[2 * p]     = expf(a);
        e[2 * p + 1] = expf(b);
    }

    #pragma unroll
    for (int n = 0; n < 8; ++n) {
        float v = e[n];
        #pragma unroll
        for (int o = 16; o > 0; o >>= 1) v += __shfl_xor_sync(0xffffffff, v, o);
        if (lane == 0) Wsum[wp][n] = v;
    }
    __syncthreads();
    if (tid < 8) {
        float s0 = 0.0f;
        #pragma unroll
        for (int w = 0; w < 8; ++w) s0 += Wsum[w][tid];
        Sinv[tid] = 1.0f / (s0 + 1e-8f);
    }
    __syncthreads();

    #pragma unroll
    for (int n = 0; n < 8; ++n)
        g_norm[(size_t)(nb + n) * R_ + r] = e[n] * Sinv[n];
}

// ---------------------------------------------------------------------------
// Kernel 3 (prep): pack coeffs + bias into bf16 m16n8k16 B-fragment order.
// ---------------------------------------------------------------------------
__global__ void __launch_bounds__(256) prep_bh_kernel(const float* __restrict__ coeffs) {
    int r = blockIdx.x, t = threadIdx.x;
    const float* src = coeffs + (size_t)r * (129 * 64);
    ull* dst = g_Bh + (size_t)r * 2048;
    for (int idx = t; idx < 2048; idx += 256) {
        int kk = idx >> 8, jt = (idx >> 5) & 7, l = idx & 31;
        int K0 = kk * 16 + (l & 3) * 2, j = jt * 8 + (l >> 2);
        uint32_t b0 = bf2(src[K0 * 64 + j],       src[(K0 + 1) * 64 + j]);
        uint32_t b1 = bf2(src[(K0 + 8) * 64 + j], src[(K0 + 9) * 64 + j]);
        ull v; asm("mov.b64 %0, {%1, %2};" : "=l"(v) : "r"(b0), "r"(b1));
        dst[idx] = v;
    }
    if (r < 8) {
        ull* bdst = g_Bbh + (size_t)r * 512;
        for (int idx = t; idx < 512; idx += 256) {
            int kk = idx >> 8, jt = (idx >> 5) & 7, l = idx & 31;
            int K0 = kk * 16 + (l & 3) * 2, j = jt * 8 + (l >> 2);
            #define BIAS(k) coeffs[(size_t)(r * 32 + (k)) * (129 * 64) + 128 * 64 + j]
            uint32_t b0 = bf2(BIAS(K0),     BIAS(K0 + 1));
            uint32_t b1 = bf2(BIAS(K0 + 8), BIAS(K0 + 9));
            #undef BIAS
            ull v; asm("mov.b64 %0, {%1, %2};" : "=l"(v) : "r"(b0), "r"(b1));
            bdst[idx] = v;
        }
    }
}

// ---------------------------------------------------------------------------
// Kernel 4: main combine. Grid (32, 8), 256 thr = 8 warps (4 m-pos x 2 n-pos).
// Warp tile: 2 m16-tiles x 4 n8-tiles; K in two 64-wide passes.
// 3-stage cp.async pipeline over 64 iterations. 3 CTAs/SM target.
// Ns holds PRE-PACKED bf16x2(norm,norm).
// ---------------------------------------------------------------------------
#define STG_ULL 1024      // 8 KB per stage
__global__ void __launch_bounds__(256, 3) main_mma_kernel(const float* __restrict__ X) {
    extern __shared__ char smc[];
    ull*      Bbuf = (ull*)smc;                        // 3 x 8 KB
    uint32_t* Ns   = (uint32_t*)(smc + 3 * 8192);      // [128][33] packed bf16x2

    const int tid  = threadIdx.x;
    const int w    = tid >> 5;
    const int lane = tid & 31;
    const int gr   = lane >> 2;
    const int gc   = lane & 3;
    const int wr   = w >> 1;          // m-position 0..3
    const int wc   = w & 1;           // n-position 0..1
    const int nb   = blockIdx.x * 128;
    const int sp   = blockIdx.y;
    const int rb   = sp * 32;

    for (int i = tid; i < 128 * 32; i += 256) {
        int n = i >> 5, rl = i & 31;
        float v = g_norm[(size_t)(nb + n) * R_ + rb + rl];
        Ns[n * 33 + rl] = bf2(v, v);
    }

    const int rA0 = 32 * wr + gr,  rB0 = rA0 + 8;
    const int rA1 = rA0 + 16,      rB1 = rB0 + 16;

    const uint32_t bsm = smem_u32(Bbuf);

    // prologue: stage iterations 0 and 1 (half 0, rules 0 and 1)
    #pragma unroll
    for (int s = 0; s < 2; ++s) {
        const ull* src = g_Bh + (size_t)(rb + s) * 2048;
        const uint32_t dst = bsm + s * 8192;
        #pragma unroll
        for (int q = 0; q < 2; ++q) {
            int c16 = tid + q * 256;
            asm volatile("cp.async.cg.shared.global [%0], [%1], 16;"
                         :: "r"(dst + c16 * 16), "l"(src + c16 * 2) : "memory");
        }
        asm volatile("cp.async.commit_group;" ::: "memory");
    }

    float acc[2][4][4];
    #pragma unroll
    for (int t = 0; t < 2; ++t)
        #pragma unroll
        for (int jt = 0; jt < 4; ++jt)
            #pragma unroll
            for (int q = 0; q < 4; ++q) acc[t][jt][q] = 0.0f;

    uint32_t x0[2][4], x1[2][4], x2[2][4], x3[2][4];

    int buf = 0;
    for (int it = 0; it < 64; ++it) {
        const int half = it >> 5;
        const int rr   = it & 31;

        if (rr == 0) {   // (re)load X fragments for this half
            #pragma unroll
            for (int t = 0; t < 2; ++t) {
                const float* pa = X + (size_t)(nb + (t ? rA1 : rA0)) * D_ + 64 * half + 2 * gc;
                const float* pb = X + (size_t)(nb + (t ? rB1 : rB0)) * D_ + 64 * half + 2 * gc;
                #pragma unroll
                for (int kk = 0; kk < 4; ++kk) {
                    float2 v;
                    v = *(const float2*)(pa + 16 * kk);     x0[t][kk] = bf2(v.x, v.y);
                    v = *(const float2*)(pa + 16 * kk + 8); x2[t][kk] = bf2(v.x, v.y);
                    v = *(const float2*)(pb + 16 * kk);     x1[t][kk] = bf2(v.x, v.y);
                    v = *(const float2*)(pb + 16 * kk + 8); x3[t][kk] = bf2(v.x, v.y);
                }
            }
        }

        if (it < 63) asm volatile("cp.async.wait_group 1;" ::: "memory");
        else         asm volatile("cp.async.wait_group 0;" ::: "memory");
        __syncthreads();

        if (it + 2 < 64) {
            const int it2 = it + 2;
            const ull* src = g_Bh + (size_t)(rb + (it2 & 31)) * 2048 + (it2 >> 5) * STG_ULL;
            int b2 = buf + 2; if (b2 >= 3) b2 -= 3;
            const uint32_t dst = bsm + b2 * 8192;
            #pragma unroll
            for (int q = 0; q < 2; ++q) {
                int c16 = tid + q * 256;
                asm volatile("cp.async.cg.shared.global [%0], [%1], 16;"
                             :: "r"(dst + c16 * 16), "l"(src + c16 * 2) : "memory");
            }
            asm volatile("cp.async.commit_group;" ::: "memory");
        }

        const uint32_t nA0 = Ns[rA0 * 33 + rr];
        const uint32_t nB0 = Ns[rB0 * 33 + rr];
        const uint32_t nA1 = Ns[rA1 * 33 + rr];
        const uint32_t nB1 = Ns[rB1 * 33 + rr];
        const ull* bb = Bbuf + buf * STG_ULL + lane;

        #pragma unroll
        for (int kk = 0; kk < 4; ++kk) {
            uint32_t a00 = hmul2(x0[0][kk], nA0);
            uint32_t a01 = hmul2(x1[0][kk], nB0);
            uint32_t a02 = hmul2(x2[0][kk], nA0);
            uint32_t a03 = hmul2(x3[0][kk], nB0);
            uint32_t a10 = hmul2(x0[1][kk], nA1);
            uint32_t a11 = hmul2(x1[1][kk], nB1);
            uint32_t a12 = hmul2(x2[1][kk], nA1);
            uint32_t a13 = hmul2(x3[1][kk], nB1);
            #pragma unroll
            for (int jt = 0; jt < 4; ++jt) {
                ull bv = bb[(kk * 8 + wc * 4 + jt) * 32];
                uint32_t b0, b1;
                u64lohi(bv, b0, b1);
                mma_bf16(acc[0][jt], a00, a01, a02, a03, b0, b1);
                mma_bf16(acc[1][jt], a10, a11, a12, a13, b0, b1);
            }
        }
        if (++buf == 3) buf = 0;
    }

    // ---- bias: 2 extra k16 steps; A pairs rebuilt from packed Ns via byte_perm
    {
        const ull* bb = g_Bbh + (size_t)sp * 512 + lane;
        #pragma unroll
        for (int kk = 0; kk < 2; ++kk) {
            const int K0 = kk * 16 + 2 * gc;
            #define NP(row, k) Ns[(row) * 33 + (k)]
            uint32_t a00 = __byte_perm(NP(rA0, K0),     NP(rA0, K0 + 1), 0x5410);
            uint32_t a01 = __byte_perm(NP(rB0, K0),     NP(rB0, K0 + 1), 0x5410);
            uint32_t a02 = __byte_perm(NP(rA0, K0 + 8), NP(rA0, K0 + 9), 0x5410);
            uint32_t a03 = __byte_perm(NP(rB0, K0 + 8), NP(rB0, K0 + 9), 0x5410);
            uint32_t a10 = __byte_perm(NP(rA1, K0),     NP(rA1, K0 + 1), 0x5410);
            uint32_t a11 = __byte_perm(NP(rB1, K0),     NP(rB1, K0 + 1), 0x5410);
            uint32_t a12 = __byte_perm(NP(rA1, K0 + 8), NP(rA1, K0 + 9), 0x5410);
            uint32_t a13 = __byte_perm(NP(rB1, K0 + 8), NP(rB1, K0 + 9), 0x5410);
            #undef NP
            #pragma unroll
            for (int jt = 0; jt < 4; ++jt) {
                ull bv = bb[(kk * 8 + wc * 4 + jt) * 32];
                uint32_t b0, b1;
                u64lohi(bv, b0, b1);
                mma_bf16(acc[0][jt], a00, a01, a02, a03, b0, b1);
                mma_bf16(acc[1][jt], a10, a11, a12, a13, b0, b1);
            }
        }
    }

    float* op = g_partial[sp];
    #pragma unroll
    for (int t = 0; t < 2; ++t) {
        const int ra = nb + (t ? rA1 : rA0);
        const int rbw = nb + (t ? rB1 : rB0);
        #pragma unroll
        for (int jt = 0; jt < 4; ++jt) {
            const int c = (wc * 4 + jt) * 8 + 2 * gc;
            *(float2*)(op + (size_t)ra * O_ + c)  = make_float2(acc[t][jt][0], acc[t][jt][1]);
            *(float2*)(op + (size_t)rbw * O_ + c) = make_float2(acc[t][jt][2], acc[t][jt][3]);
        }
    }
}

// ---------------------------------------------------------------------------
// Kernel 5: softmax, warp per row (pure shfl), 8 rows/block.
// ---------------------------------------------------------------------------
__global__ void __launch_bounds__(256) softmax_kernel(float* __restrict__ out) {
    const int lane = threadIdx.x & 31;
    const int n = blockIdx.x * 8 + (threadIdx.x >> 5);
    const size_t base = (size_t)n * O_;

    float l0 = 0.0f, l1 = 0.0f;
    #pragma unroll
    for (int s = 0; s < 8; ++s) {
        l0 += g_partial[s][base + lane];
        l1 += g_partial[s][base + lane + 32];
    }
    float m = fmaxf(l0, l1);
    #pragma unroll
    for (int o = 16; o > 0; o >>= 1) m = fmaxf(m, __shfl_xor_sync(0xffffffff, m, o));
    float e0 = expf(l0 - m), e1 = expf(l1 - m);
    float s = e0 + e1;
    #pragma unroll
    for (int o = 16; o > 0; o >>= 1) s += __shfl_xor_sync(0xffffffff, s, o);
    float inv = 1.0f / s;
    out[base + lane]      = e0 * inv;
    out[base + lane + 32] = e1 * inv;
}

// ---------------------------------------------------------------------------
extern "C" void kernel_launch(void* const* d_in, const int* in_sizes, int n_in,
                              void* d_out, int out_size) {
    const float* X       = (const float*)d_in[0];
    const float* centers = (const float*)d_in[1];
    const float* sigmas  = (const float*)d_in[2];
    const float* coeffs  = (const float*)d_in[3];
    float* out = (float*)d_out;

    const int SMEM_M = 3 * 8192 + 128 * 33 * (int)sizeof(uint32_t);   // 41472 B
    cudaFuncSetAttribute(main_mma_kernel, cudaFuncAttributeMaxDynamicSharedMemorySize, SMEM_M);

    prep_kernel<<<R_, D_>>>(centers, sigmas);                 // 0
    strengths_kernel<<<N_ / 8, 256>>>(X);                     // 1
    prep_bh_kernel<<<R_, 256>>>(coeffs);                      // 2
    main_mma_kernel<<<dim3(N_ / 128, 8), 256, SMEM_M>>>(X);   // 3  <- ncu capture slot
    softmax_kernel<<<N_ / 8, 256>>>(out);                     // 4
}

// round 10
// speedup vs baseline: 1.1402x; 1.1402x over previous
#include <cuda_runtime.h>
#include <cstdint>

#define N_  4096
#define D_  128
#define R_  256
#define O_  64

typedef unsigned long long ull;

// ---------------- scratch (__device__ globals) -------------------------------
__device__ float g_w4[D_ * R_];
__device__ float g_u4[D_ * R_];
__device__ float g_k[R_];
__device__ float g_norm[(size_t)N_ * R_];              // [n][r]
__device__ __align__(16) ull g_Bh[(size_t)R_ * 2048];  // bf16 B frags [r][half2][kk4][jt8][lane32]
__device__ __align__(16) ull g_Bbh[8 * 512];           // bf16 bias frags [sp][kk2][jt8][lane32]
__device__ float g_partial[8][(size_t)N_ * O_];

// ---------------- helpers ----------------------------------------------------
__device__ __forceinline__ ull pack2(float lo, float hi) {
    ull r; asm("mov.b64 %0, {%1, %2};" : "=l"(r) : "f"(lo), "f"(hi)); return r;
}
__device__ __forceinline__ void unpack2(ull v, float& lo, float& hi) {
    asm("mov.b64 {%0, %1}, %2;" : "=f"(lo), "=f"(hi) : "l"(v));
}
__device__ __forceinline__ ull fma2(ull a, ull b, ull c) {
    ull d; asm("fma.rn.f32x2 %0, %1, %2, %3;" : "=l"(d) : "l"(a), "l"(b), "l"(c)); return d;
}
__device__ __forceinline__ uint32_t bf2(float a, float b) {   // lo=a, hi=b
    uint32_t r; asm("cvt.rn.bf16x2.f32 %0, %1, %2;" : "=r"(r) : "f"(b), "f"(a)); return r;
}
__device__ __forceinline__ uint32_t hmul2(uint32_t a, uint32_t b) {
    uint32_t r; asm("mul.bf16x2 %0, %1, %2;" : "=r"(r) : "r"(a), "r"(b)); return r;
}
__device__ __forceinline__ void u64lohi(ull v, uint32_t& lo, uint32_t& hi) {
    asm("mov.b64 {%0, %1}, %2;" : "=r"(lo), "=r"(hi) : "l"(v));
}
__device__ __forceinline__ uint32_t smem_u32(const void* p) {
    uint32_t a;
    asm("{ .reg .u64 t; cvta.to.shared.u64 t, %1; cvt.u32.u64 %0, t; }" : "=r"(a) : "l"(p));
    return a;
}
__device__ __forceinline__ void mma_bf16(float* c,
                                         uint32_t a0, uint32_t a1, uint32_t a2, uint32_t a3,
                                         uint32_t b0, uint32_t b1) {
    asm volatile(
        "mma.sync.aligned.m16n8k16.row.col.f32.bf16.bf16.f32 "
        "{%0,%1,%2,%3}, {%4,%5,%6,%7}, {%8,%9}, {%0,%1,%2,%3};"
        : "+f"(c[0]), "+f"(c[1]), "+f"(c[2]), "+f"(c[3])
        : "r"(a0), "r"(a1), "r"(a2), "r"(a3), "r"(b0), "r"(b1));
}

// ---------------------------------------------------------------------------
// Kernel 1: membership params -> quad layout
// ---------------------------------------------------------------------------
__global__ void prep_kernel(const float* __restrict__ centers,
                            const float* __restrict__ sigmas) {
    int r = blockIdx.x, d = threadIdx.x;
    float c  = centers[r * D_ + d];
    float sg = sigmas [r * D_ + d];
    float inv = 1.0f / (sg * sg);
    float w = 0.5f * inv;
    float u = c * inv;
    int q = (d >> 2) * (R_ * 4) + r * 4 + (d & 3);
    g_w4[q] = w;
    g_u4[q] = u;
    __shared__ float red[128];
    red[d] = w * c * c;
    __syncthreads();
    for (int s = 64; s > 0; s >>= 1) { if (d < s) red[d] += red[d + s]; __syncthreads(); }
    if (d == 0) g_k[r] = red[0];
}

// ---------------------------------------------------------------------------
// Kernel 2: strengths + normalization. 512 blocks x 256 thr, 8 rows/block.
// ---------------------------------------------------------------------------
#define XSTR 10
__global__ void __launch_bounds__(256) strengths_kernel(const float* __restrict__ X) {
    __shared__ float Xs[128 * XSTR];
    __shared__ float Wsum[8][8];
    __shared__ float Sinv[8];

    const int tid = threadIdx.x;
    const int nb  = blockIdx.x * 8;
    const int lane = tid & 31, wp = tid >> 5;

    for (int idx = tid; idx < 8 * 128; idx += 256) {
        int n = idx >> 7, d = idx & 127;
        Xs[d * XSTR + n] = X[(size_t)(nb + n) * D_ + d];
    }
    __syncthreads();

    const int r = tid;
    float kk = g_k[r];
    ull s[4];
    ull init = pack2(-kk, -kk);
    #pragma unroll
    for (int p = 0; p < 4; ++p) s[p] = init;

    #pragma unroll 4
    for (int c = 0; c < 32; ++c) {
        float4 w4 = *(const float4*)&g_w4[(c * R_ + r) * 4];
        float4 u4 = *(const float4*)&g_u4[(c * R_ + r) * 4];
        const float wv[4] = {w4.x, w4.y, w4.z, w4.w};
        const float uv[4] = {u4.x, u4.y, u4.z, u4.w};
        #pragma unroll
        for (int dd = 0; dd < 4; ++dd) {
            ull w2 = pack2(-wv[dd], -wv[dd]);
            ull u2 = pack2(uv[dd], uv[dd]);
            const float* xrow = &Xs[(c * 4 + dd) * XSTR];
            #pragma unroll
            for (int p = 0; p < 4; ++p) {
                ull xp = *(const ull*)&xrow[p * 2];
                ull t  = fma2(w2, xp, u2);
                s[p]   = fma2(t, xp, s[p]);
            }
        }
    }

    float e[8];
    #pragma unroll
    for (int p = 0; p < 4; ++p) {
        float a, b;
        unpack2(s[p], a, b);
        e[2 * p]     = expf(a);
        e[2 * p + 1] = expf(b);
    }

    #pragma unroll
    for (int n = 0; n < 8; ++n) {
        float v = e[n];
        #pragma unroll
        for (int o = 16; o > 0; o >>= 1) v += __shfl_xor_sync(0xffffffff, v, o);
        if (lane == 0) Wsum[wp][n] = v;
    }
    __syncthreads();
    if (tid < 8) {
        float s0 = 0.0f;
        #pragma unroll
        for (int w = 0; w < 8; ++w) s0 += Wsum[w][tid];
        Sinv[tid] = 1.0f / (s0 + 1e-8f);
    }
    __syncthreads();

    #pragma unroll
    for (int n = 0; n < 8; ++n)
        g_norm[(size_t)(nb + n) * R_ + r] = e[n] * Sinv[n];
}

// ---------------------------------------------------------------------------
// Kernel 3 (prep): pack coeffs + bias into bf16 m16n8k16 B-fragment order.
// ---------------------------------------------------------------------------
__global__ void __launch_bounds__(256) prep_bh_kernel(const float* __restrict__ coeffs) {
    int r = blockIdx.x, t = threadIdx.x;
    const float* src = coeffs + (size_t)r * (129 * 64);
    ull* dst = g_Bh + (size_t)r * 2048;
    for (int idx = t; idx < 2048; idx += 256) {
        int kk = idx >> 8, jt = (idx >> 5) & 7, l = idx & 31;
        int K0 = kk * 16 + (l & 3) * 2, j = jt * 8 + (l >> 2);
        uint32_t b0 = bf2(src[K0 * 64 + j],       src[(K0 + 1) * 64 + j]);
        uint32_t b1 = bf2(src[(K0 + 8) * 64 + j], src[(K0 + 9) * 64 + j]);
        ull v; asm("mov.b64 %0, {%1, %2};" : "=l"(v) : "r"(b0), "r"(b1));
        dst[idx] = v;
    }
    if (r < 8) {
        ull* bdst = g_Bbh + (size_t)r * 512;
        for (int idx = t; idx < 512; idx += 256) {
            int kk = idx >> 8, jt = (idx >> 5) & 7, l = idx & 31;
            int K0 = kk * 16 + (l & 3) * 2, j = jt * 8 + (l >> 2);
            #define BIAS(k) coeffs[(size_t)(r * 32 + (k)) * (129 * 64) + 128 * 64 + j]
            uint32_t b0 = bf2(BIAS(K0),     BIAS(K0 + 1));
            uint32_t b1 = bf2(BIAS(K0 + 8), BIAS(K0 + 9));
            #undef BIAS
            ull v; asm("mov.b64 %0, {%1, %2};" : "=l"(v) : "r"(b0), "r"(b1));
            bdst[idx] = v;
        }
    }
}

// ---------------------------------------------------------------------------
// Kernel 4: main combine. Grid (32, 8), 256 thr = 8 warps (4 m-pos x 2 n-pos).
// Warp tile: 2 m16-tiles x 4 n8-tiles; K in two 64-wide passes.
// Stage = 4 rules x one K-half = 32 KB; 3-stage cp.async pipeline;
// 16 iterations -> 128 MMAs/warp between barriers.
// ---------------------------------------------------------------------------
#define STAGE_ULL 4096            // 32 KB per stage
__global__ void __launch_bounds__(256, 2) main_mma_kernel(const float* __restrict__ X) {
    extern __shared__ char smc[];
    ull*      Bbuf = (ull*)smc;                            // 3 x 32 KB
    uint32_t* Ns   = (uint32_t*)(smc + 3 * 32768);         // [128][33] packed bf16x2

    const int tid  = threadIdx.x;
    const int w    = tid >> 5;
    const int lane = tid & 31;
    const int gr   = lane >> 2;
    const int gc   = lane & 3;
    const int wr   = w >> 1;          // m-position 0..3
    const int wc   = w & 1;           // n-position 0..1
    const int nb   = blockIdx.x * 128;
    const int sp   = blockIdx.y;
    const int rb   = sp * 32;

    for (int i = tid; i < 128 * 32; i += 256) {
        int n = i >> 5, rl = i & 31;
        float v = g_norm[(size_t)(nb + n) * R_ + rb + rl];
        Ns[n * 33 + rl] = bf2(v, v);
    }

    const int rA0 = 32 * wr + gr,  rB0 = rA0 + 8;
    const int rA1 = rA0 + 16,      rB1 = rB0 + 16;

    const uint32_t bsm = smem_u32(Bbuf);

    // stage loader: iteration 'it2' covers rules rq*4..rq*4+3, half = it2>>3
    #define STAGE_LOAD(it2, slot) do {                                            \
        const int _half = (it2) >> 3, _rq = (it2) & 7;                            \
        const ull* _base = g_Bh + (size_t)(rb + _rq * 4) * 2048 + _half * 1024;   \
        const uint32_t _dst = bsm + (slot) * 32768;                               \
        _Pragma("unroll")                                                         \
        for (int _q = 0; _q < 8; ++_q) {                                          \
            int _c16 = tid + _q * 256;              /* 0..2047 */                 \
            int _rl  = _c16 >> 9;                                                 \
            int _rem = _c16 & 511;                                                \
            const ull* _src = _base + (size_t)_rl * 2048 + _rem * 2;              \
            asm volatile("cp.async.cg.shared.global [%0], [%1], 16;"              \
                         :: "r"(_dst + _c16 * 16), "l"(_src) : "memory");         \
        }                                                                         \
        asm volatile("cp.async.commit_group;" ::: "memory");                      \
    } while (0)

    // prologue: stages for iterations 0 and 1
    STAGE_LOAD(0, 0);
    STAGE_LOAD(1, 1);

    float acc[2][4][4];
    #pragma unroll
    for (int t = 0; t < 2; ++t)
        #pragma unroll
        for (int jt = 0; jt < 4; ++jt)
            #pragma unroll
            for (int q = 0; q < 4; ++q) acc[t][jt][q] = 0.0f;

    uint32_t x0[2][4], x1[2][4], x2[2][4], x3[2][4];

    int buf = 0;
    for (int it = 0; it < 16; ++it) {
        const int half = it >> 3;

        if ((it & 7) == 0) {   // (re)load X fragments for this half (it = 0, 8)
            #pragma unroll
            for (int t = 0; t < 2; ++t) {
                const float* pa = X + (size_t)(nb + (t ? rA1 : rA0)) * D_ + 64 * half + 2 * gc;
                const float* pb = X + (size_t)(nb + (t ? rB1 : rB0)) * D_ + 64 * half + 2 * gc;
                #pragma unroll
                for (int kk = 0; kk < 4; ++kk) {
                    float2 v;
                    v = *(const float2*)(pa + 16 * kk);     x0[t][kk] = bf2(v.x, v.y);
                    v = *(const float2*)(pa + 16 * kk + 8); x2[t][kk] = bf2(v.x, v.y);
                    v = *(const float2*)(pb + 16 * kk);     x1[t][kk] = bf2(v.x, v.y);
                    v = *(const float2*)(pb + 16 * kk + 8); x3[t][kk] = bf2(v.x, v.y);
                }
            }
        }

        if (it < 15) asm volatile("cp.async.wait_group 1;" ::: "memory");
        else         asm volatile("cp.async.wait_group 0;" ::: "memory");
        __syncthreads();

        if (it + 2 < 16) {
            int b2 = buf + 2; if (b2 >= 3) b2 -= 3;
            STAGE_LOAD(it + 2, b2);
        }

        // ---- compute 4 rules from stage 'buf'
        const int rq = it & 7;
        #pragma unroll
        for (int rl = 0; rl < 4; ++rl) {
            const int rr = rq * 4 + rl;
            const uint32_t nA0 = Ns[rA0 * 33 + rr];
            const uint32_t nB0 = Ns[rB0 * 33 + rr];
            const uint32_t nA1 = Ns[rA1 * 33 + rr];
            const uint32_t nB1 = Ns[rB1 * 33 + rr];
            const ull* bb = Bbuf + buf * STAGE_ULL + rl * 1024 + lane;

            #pragma unroll
            for (int kk = 0; kk < 4; ++kk) {
                uint32_t a00 = hmul2(x0[0][kk], nA0);
                uint32_t a01 = hmul2(x1[0][kk], nB0);
                uint32_t a02 = hmul2(x2[0][kk], nA0);
                uint32_t a03 = hmul2(x3[0][kk], nB0);
                uint32_t a10 = hmul2(x0[1][kk], nA1);
                uint32_t a11 = hmul2(x1[1][kk], nB1);
                uint32_t a12 = hmul2(x2[1][kk], nA1);
                uint32_t a13 = hmul2(x3[1][kk], nB1);
                #pragma unroll
                for (int jt = 0; jt < 4; ++jt) {
                    ull bv = bb[(kk * 8 + wc * 4 + jt) * 32];
                    uint32_t b0, b1;
                    u64lohi(bv, b0, b1);
                    mma_bf16(acc[0][jt], a00, a01, a02, a03, b0, b1);
                    mma_bf16(acc[1][jt], a10, a11, a12, a13, b0, b1);
                }
            }
        }
        if (++buf == 3) buf = 0;
    }

    // ---- bias: 2 extra k16 steps; A pairs rebuilt from packed Ns via byte_perm
    {
        const ull* bb = g_Bbh + (size_t)sp * 512 + lane;
        #pragma unroll
        for (int kk = 0; kk < 2; ++kk) {
            const int K0 = kk * 16 + 2 * gc;
            #define NP(row, k) Ns[(row) * 33 + (k)]
            uint32_t a00 = __byte_perm(NP(rA0, K0),     NP(rA0, K0 + 1), 0x5410);
            uint32_t a01 = __byte_perm(NP(rB0, K0),     NP(rB0, K0 + 1), 0x5410);
            uint32_t a02 = __byte_perm(NP(rA0, K0 + 8), NP(rA0, K0 + 9), 0x5410);
            uint32_t a03 = __byte_perm(NP(rB0, K0 + 8), NP(rB0, K0 + 9), 0x5410);
            uint32_t a10 = __byte_perm(NP(rA1, K0),     NP(rA1, K0 + 1), 0x5410);
            uint32_t a11 = __byte_perm(NP(rB1, K0),     NP(rB1, K0 + 1), 0x5410);
            uint32_t a12 = __byte_perm(NP(rA1, K0 + 8), NP(rA1, K0 + 9), 0x5410);
            uint32_t a13 = __byte_perm(NP(rB1, K0 + 8), NP(rB1, K0 + 9), 0x5410);
            #undef NP
            #pragma unroll
            for (int jt = 0; jt < 4; ++jt) {
                ull bv = bb[(kk * 8 + wc * 4 + jt) * 32];
                uint32_t b0, b1;
                u64lohi(bv, b0, b1);
                mma_bf16(acc[0][jt], a00, a01, a02, a03, b0, b1);
                mma_bf16(acc[1][jt], a10, a11, a12, a13, b0, b1);
            }
        }
    }

    float* op = g_partial[sp];
    #pragma unroll
    for (int t = 0; t < 2; ++t) {
        const int ra = nb + (t ? rA1 : rA0);
        const int rbw = nb + (t ? rB1 : rB0);
        #pragma unroll
        for (int jt = 0; jt < 4; ++jt) {
            const int c = (wc * 4 + jt) * 8 + 2 * gc;
            *(float2*)(op + (size_t)ra * O_ + c)  = make_float2(acc[t][jt][0], acc[t][jt][1]);
            *(float2*)(op + (size_t)rbw * O_ + c) = make_float2(acc[t][jt][2], acc[t][jt][3]);
        }
    }
}

// ---------------------------------------------------------------------------
// Kernel 5: softmax, warp per row (pure shfl), 8 rows/block.
// ---------------------------------------------------------------------------
__global__ void __launch_bounds__(256) softmax_kernel(float* __restrict__ out) {
    const int lane = threadIdx.x & 31;
    const int n = blockIdx.x * 8 + (threadIdx.x >> 5);
    const size_t base = (size_t)n * O_;

    float l0 = 0.0f, l1 = 0.0f;
    #pragma unroll
    for (int s = 0; s < 8; ++s) {
        l0 += g_partial[s][base + lane];
        l1 += g_partial[s][base + lane + 32];
    }
    float m = fmaxf(l0, l1);
    #pragma unroll
    for (int o = 16; o > 0; o >>= 1) m = fmaxf(m, __shfl_xor_sync(0xffffffff, m, o));
    float e0 = expf(l0 - m), e1 = expf(l1 - m);
    float s = e0 + e1;
    #pragma unroll
    for (int o = 16; o > 0; o >>= 1) s += __shfl_xor_sync(0xffffffff, s, o);
    float inv = 1.0f / s;
    out[base + lane]      = e0 * inv;
    out[base + lane + 32] = e1 * inv;
}

// ---------------------------------------------------------------------------
extern "C" void kernel_launch(void* const* d_in, const int* in_sizes, int n_in,
                              void* d_out, int out_size) {
    const float* X       = (const float*)d_in[0];
    const float* centers = (const float*)d_in[1];
    const float* sigmas  = (const float*)d_in[2];
    const float* coeffs  = (const float*)d_in[3];
    float* out = (float*)d_out;

    const int SMEM_M = 3 * 32768 + 128 * 33 * (int)sizeof(uint32_t);   // 115200 B
    cudaFuncSetAttribute(main_mma_kernel, cudaFuncAttributeMaxDynamicSharedMemorySize, SMEM_M);

    prep_kernel<<<R_, D_>>>(centers, sigmas);                 // 0
    strengths_kernel<<<N_ / 8, 256>>>(X);                     // 1
    prep_bh_kernel<<<R_, 256>>>(coeffs);                      // 2
    main_mma_kernel<<<dim3(N_ / 128, 8), 256, SMEM_M>>>(X);   // 3  <- ncu capture slot
    softmax_kernel<<<N_ / 8, 256>>>(out);                     // 4
}

// round 11
// speedup vs baseline: 1.1428x; 1.0022x over previous
#include <cuda_runtime.h>
#include <cstdint>

#define N_  4096
#define D_  128
#define R_  256
#define O_  64

typedef unsigned long long ull;

// ---------------- scratch (__device__ globals) -------------------------------
__device__ float g_w4[D_ * R_];
__device__ float g_u4[D_ * R_];
__device__ float g_k[R_];
__device__ float g_norm[(size_t)N_ * R_];              // [n][r]
__device__ __align__(16) ull g_Bh[(size_t)R_ * 2048];  // bf16 B frags [r][half2][kk4][jt8][lane32]
__device__ __align__(16) ull g_Bbh[8 * 512];           // bf16 bias frags [sp][kk2][jt8][lane32]
__device__ float g_partial[8][(size_t)N_ * O_];

// ---------------- helpers ----------------------------------------------------
__device__ __forceinline__ ull pack2(float lo, float hi) {
    ull r; asm("mov.b64 %0, {%1, %2};" : "=l"(r) : "f"(lo), "f"(hi)); return r;
}
__device__ __forceinline__ void unpack2(ull v, float& lo, float& hi) {
    asm("mov.b64 {%0, %1}, %2;" : "=f"(lo), "=f"(hi) : "l"(v));
}
__device__ __forceinline__ ull fma2(ull a, ull b, ull c) {
    ull d; asm("fma.rn.f32x2 %0, %1, %2, %3;" : "=l"(d) : "l"(a), "l"(b), "l"(c)); return d;
}
__device__ __forceinline__ uint32_t bf2(float a, float b) {   // lo=a, hi=b
    uint32_t r; asm("cvt.rn.bf16x2.f32 %0, %1, %2;" : "=r"(r) : "f"(b), "f"(a)); return r;
}
__device__ __forceinline__ void u64lohi(ull v, uint32_t& lo, uint32_t& hi) {
    asm("mov.b64 {%0, %1}, %2;" : "=r"(lo), "=r"(hi) : "l"(v));
}
__device__ __forceinline__ uint32_t smem_u32(const void* p) {
    uint32_t a;
    asm("{ .reg .u64 t; cvta.to.shared.u64 t, %1; cvt.u32.u64 %0, t; }" : "=r"(a) : "l"(p));
    return a;
}
// accumulate: C += A*B
__device__ __forceinline__ void mma_bf16(float* c,
                                         uint32_t a0, uint32_t a1, uint32_t a2, uint32_t a3,
                                         uint32_t b0, uint32_t b1) {
    asm volatile(
        "mma.sync.aligned.m16n8k16.row.col.f32.bf16.bf16.f32 "
        "{%0,%1,%2,%3}, {%4,%5,%6,%7}, {%8,%9}, {%0,%1,%2,%3};"
        : "+f"(c[0]), "+f"(c[1]), "+f"(c[2]), "+f"(c[3])
        : "r"(a0), "r"(a1), "r"(a2), "r"(a3), "r"(b0), "r"(b1));
}
// fresh write: D = A*B + 0 (no dependence on previous D)
__device__ __forceinline__ void mma_bf16_init(float* d,
                                              uint32_t a0, uint32_t a1, uint32_t a2, uint32_t a3,
                                              uint32_t b0, uint32_t b1) {
    asm volatile(
        "mma.sync.aligned.m16n8k16.row.col.f32.bf16.bf16.f32 "
        "{%0,%1,%2,%3}, {%4,%5,%6,%7}, {%8,%9}, {%10,%10,%10,%10};"
        : "=f"(d[0]), "=f"(d[1]), "=f"(d[2]), "=f"(d[3])
        : "r"(a0), "r"(a1), "r"(a2), "r"(a3), "r"(b0), "r"(b1), "f"(0.0f));
}

// ---------------------------------------------------------------------------
// Kernel 1: membership params -> quad layout
// ---------------------------------------------------------------------------
__global__ void prep_kernel(const float* __restrict__ centers,
                            const float* __restrict__ sigmas) {
    int r = blockIdx.x, d = threadIdx.x;
    float c  = centers[r * D_ + d];
    float sg = sigmas [r * D_ + d];
    float inv = 1.0f / (sg * sg);
    float w = 0.5f * inv;
    float u = c * inv;
    int q = (d >> 2) * (R_ * 4) + r * 4 + (d & 3);
    g_w4[q] = w;
    g_u4[q] = u;
    __shared__ float red[128];
    red[d] = w * c * c;
    __syncthreads();
    for (int s = 64; s > 0; s >>= 1) { if (d < s) red[d] += red[d + s]; __syncthreads(); }
    if (d == 0) g_k[r] = red[0];
}

// ---------------------------------------------------------------------------
// Kernel 2: strengths + normalization. 256 blocks x 256 thr, 16 rows/block
// (fewer blocks -> 4x less parameter reload traffic from L2).
// ---------------------------------------------------------------------------
#define XSTR 18
__global__ void __launch_bounds__(256) strengths_kernel(const float* __restrict__ X) {
    __shared__ float Xs[128 * XSTR];
    __shared__ float Wsum[8][16];
    __shared__ float Sinv[16];

    const int tid = threadIdx.x;
    const int nb  = blockIdx.x * 16;
    const int lane = tid & 31, wp = tid >> 5;

    for (int idx = tid; idx < 16 * 128; idx += 256) {
        int n = idx >> 7, d = idx & 127;
        Xs[d * XSTR + n] = X[(size_t)(nb + n) * D_ + d];
    }
    __syncthreads();

    const int r = tid;
    float kk = g_k[r];
    ull s[8];
    ull init = pack2(-kk, -kk);
    #pragma unroll
    for (int p = 0; p < 8; ++p) s[p] = init;

    #pragma unroll 4
    for (int c = 0; c < 32; ++c) {
        float4 w4 = *(const float4*)&g_w4[(c * R_ + r) * 4];
        float4 u4 = *(const float4*)&g_u4[(c * R_ + r) * 4];
        const float wv[4] = {w4.x, w4.y, w4.z, w4.w};
        const float uv[4] = {u4.x, u4.y, u4.z, u4.w};
        #pragma unroll
        for (int dd = 0; dd < 4; ++dd) {
            ull w2 = pack2(-wv[dd], -wv[dd]);
            ull u2 = pack2(uv[dd], uv[dd]);
            const float* xrow = &Xs[(c * 4 + dd) * XSTR];
            #pragma unroll
            for (int p = 0; p < 8; ++p) {
                ull xp = *(const ull*)&xrow[p * 2];
                ull t  = fma2(w2, xp, u2);
                s[p]   = fma2(t, xp, s[p]);
            }
        }
    }

    float e[16];
    #pragma unroll
    for (int p = 0; p < 8; ++p) {
        float a, b;
        unpack2(s[p], a, b);
        e[2 * p]     = expf(a);
        e[2 * p + 1] = expf(b);
    }

    #pragma unroll
    for (int n = 0; n < 16; ++n) {
        float v = e[n];
        #pragma unroll
        for (int o = 16; o > 0; o >>= 1) v += __shfl_xor_sync(0xffffffff, v, o);
        if (lane == 0) Wsum[wp][n] = v;
    }
    __syncthreads();
    if (tid < 16) {
        float s0 = 0.0f;
        #pragma unroll
        for (int w = 0; w < 8; ++w) s0 += Wsum[w][tid];
        Sinv[tid] = 1.0f / (s0 + 1e-8f);
    }
    __syncthreads();

    #pragma unroll
    for (int n = 0; n < 16; ++n)
        g_norm[(size_t)(nb + n) * R_ + r] = e[n] * Sinv[n];
}

// ---------------------------------------------------------------------------
// Kernel 3 (prep): pack coeffs + bias into bf16 m16n8k16 B-fragment order.
// ---------------------------------------------------------------------------
__global__ void __launch_bounds__(256) prep_bh_kernel(const float* __restrict__ coeffs) {
    int r = blockIdx.x, t = threadIdx.x;
    const float* src = coeffs + (size_t)r * (129 * 64);
    ull* dst = g_Bh + (size_t)r * 2048;
    for (int idx = t; idx < 2048; idx += 256) {
        int kk = idx >> 8, jt = (idx >> 5) & 7, l = idx & 31;
        int K0 = kk * 16 + (l & 3) * 2, j = jt * 8 + (l >> 2);
        uint32_t b0 = bf2(src[K0 * 64 + j],       src[(K0 + 1) * 64 + j]);
        uint32_t b1 = bf2(src[(K0 + 8) * 64 + j], src[(K0 + 9) * 64 + j]);
        ull v; asm("mov.b64 %0, {%1, %2};" : "=l"(v) : "r"(b0), "r"(b1));
        dst[idx] = v;
    }
    if (r < 8) {
        ull* bdst = g_Bbh + (size_t)r * 512;
        for (int idx = t; idx < 512; idx += 256) {
            int kk = idx >> 8, jt = (idx >> 5) & 7, l = idx & 31;
            int K0 = kk * 16 + (l & 3) * 2, j = jt * 8 + (l >> 2);
            #define BIAS(k) coeffs[(size_t)(r * 32 + (k)) * (129 * 64) + 128 * 64 + j]
            uint32_t b0 = bf2(BIAS(K0),     BIAS(K0 + 1));
            uint32_t b1 = bf2(BIAS(K0 + 8), BIAS(K0 + 9));
            #undef BIAS
            ull v; asm("mov.b64 %0, {%1, %2};" : "=l"(v) : "r"(b0), "r"(b1));
            bdst[idx] = v;
        }
    }
}

// ---------------------------------------------------------------------------
// Kernel 4: main combine, SCALE-AFTER-MMA variant.
// Grid (32, 8), 256 thr = 8 warps (4 m-pos x 2 n-pos).
// Per rule-half: P = X_half * C_r,half (X frags constant in registers, NO
// per-MMA multiply on critical path), then acc += norm * P (32 FFMAs).
// Stage = 4 rules x one K-half = 32 KB; 3-stage cp.async pipeline.
// ---------------------------------------------------------------------------
#define STAGE_ULL 4096            // 32 KB per stage
__global__ void __launch_bounds__(256, 2) main_mma_kernel(const float* __restrict__ X) {
    extern __shared__ char smc[];
    ull*   Bbuf = (ull*)smc;                            // 3 x 32 KB
    float* Ns   = (float*)(smc + 3 * 32768);            // [128][33] float norms

    const int tid  = threadIdx.x;
    const int w    = tid >> 5;
    const int lane = tid & 31;
    const int gr   = lane >> 2;
    const int gc   = lane & 3;
    const int wr   = w >> 1;          // m-position 0..3
    const int wc   = w & 1;           // n-position 0..1
    const int nb   = blockIdx.x * 128;
    const int sp   = blockIdx.y;
    const int rb   = sp * 32;

    for (int i = tid; i < 128 * 32; i += 256) {
        int n = i >> 5, rl = i & 31;
        Ns[n * 33 + rl] = g_norm[(size_t)(nb + n) * R_ + rb + rl];
    }

    const int rA0 = 32 * wr + gr,  rB0 = rA0 + 8;
    const int rA1 = rA0 + 16,      rB1 = rB0 + 16;

    const uint32_t bsm = smem_u32(Bbuf);

    #define STAGE_LOAD(it2, slot) do {                                            \
        const int _half = (it2) >> 3, _rq = (it2) & 7;                            \
        const ull* _base = g_Bh + (size_t)(rb + _rq * 4) * 2048 + _half * 1024;   \
        const uint32_t _dst = bsm + (slot) * 32768;                               \
        _Pragma("unroll")                                                         \
        for (int _q = 0; _q < 8; ++_q) {                                          \
            int _c16 = tid + _q * 256;              /* 0..2047 */                 \
            int _rl  = _c16 >> 9;                                                 \
            int _rem = _c16 & 511;                                                \
            const ull* _src = _base + (size_t)_rl * 2048 + _rem * 2;              \
            asm volatile("cp.async.cg.shared.global [%0], [%1], 16;"              \
                         :: "r"(_dst + _c16 * 16), "l"(_src) : "memory");         \
        }                                                                         \
        asm volatile("cp.async.commit_group;" ::: "memory");                      \
    } while (0)

    STAGE_LOAD(0, 0);
    STAGE_LOAD(1, 1);

    float acc[2][4][4];
    #pragma unroll
    for (int t = 0; t < 2; ++t)
        #pragma unroll
        for (int jt = 0; jt < 4; ++jt)
            #pragma unroll
            for (int q = 0; q < 4; ++q) acc[t][jt][q] = 0.0f;

    // X fragments for current half (CONSTANT across the 8 rule-iterations)
    uint32_t x0[2][4], x1[2][4], x2[2][4], x3[2][4];

    int buf = 0;
    for (int it = 0; it < 16; ++it) {
        const int half = it >> 3;

        if ((it & 7) == 0) {   // (re)load X fragments (it = 0, 8)
            #pragma unroll
            for (int t = 0; t < 2; ++t) {
                const float* pa = X + (size_t)(nb + (t ? rA1 : rA0)) * D_ + 64 * half + 2 * gc;
                const float* pb = X + (size_t)(nb + (t ? rB1 : rB0)) * D_ + 64 * half + 2 * gc;
                #pragma unroll
                for (int kk = 0; kk < 4; ++kk) {
                    float2 v;
                    v = *(const float2*)(pa + 16 * kk);     x0[t][kk] = bf2(v.x, v.y);
                    v = *(const float2*)(pa + 16 * kk + 8); x2[t][kk] = bf2(v.x, v.y);
                    v = *(const float2*)(pb + 16 * kk);     x1[t][kk] = bf2(v.x, v.y);
                    v = *(const float2*)(pb + 16 * kk + 8); x3[t][kk] = bf2(v.x, v.y);
                }
            }
        }

        if (it < 15) asm volatile("cp.async.wait_group 1;" ::: "memory");
        else         asm volatile("cp.async.wait_group 0;" ::: "memory");
        __syncthreads();

        if (it + 2 < 16) {
            int b2 = buf + 2; if (b2 >= 3) b2 -= 3;
            STAGE_LOAD(it + 2, b2);
        }

        const int rq = it & 7;
        #pragma unroll
        for (int rl = 0; rl < 4; ++rl) {
            const int rr = rq * 4 + rl;
            const ull* bb = Bbuf + buf * STAGE_ULL + rl * 1024 + lane;

            float P[2][4][4];
            #pragma unroll
            for (int kk = 0; kk < 4; ++kk) {
                #pragma unroll
                for (int jt = 0; jt < 4; ++jt) {
                    ull bv = bb[(kk * 8 + wc * 4 + jt) * 32];
                    uint32_t b0, b1;
                    u64lohi(bv, b0, b1);
                    if (kk == 0) {
                        mma_bf16_init(P[0][jt], x0[0][kk], x1[0][kk], x2[0][kk], x3[0][kk], b0, b1);
                        mma_bf16_init(P[1][jt], x0[1][kk], x1[1][kk], x2[1][kk], x3[1][kk], b0, b1);
                    } else {
                        mma_bf16(P[0][jt], x0[0][kk], x1[0][kk], x2[0][kk], x3[0][kk], b0, b1);
                        mma_bf16(P[1][jt], x0[1][kk], x1[1][kk], x2[1][kk], x3[1][kk], b0, b1);
                    }
                }
            }

            const float nA0 = Ns[rA0 * 33 + rr];
            const float nB0 = Ns[rB0 * 33 + rr];
            const float nA1 = Ns[rA1 * 33 + rr];
            const float nB1 = Ns[rB1 * 33 + rr];
            #pragma unroll
            for (int jt = 0; jt < 4; ++jt) {
                acc[0][jt][0] = fmaf(nA0, P[0][jt][0], acc[0][jt][0]);
                acc[0][jt][1] = fmaf(nA0, P[0][jt][1], acc[0][jt][1]);
                acc[0][jt][2] = fmaf(nB0, P[0][jt][2], acc[0][jt][2]);
                acc[0][jt][3] = fmaf(nB0, P[0][jt][3], acc[0][jt][3]);
                acc[1][jt][0] = fmaf(nA1, P[1][jt][0], acc[1][jt][0]);
                acc[1][jt][1] = fmaf(nA1, P[1][jt][1], acc[1][jt][1]);
                acc[1][jt][2] = fmaf(nB1, P[1][jt][2], acc[1][jt][2]);
                acc[1][jt][3] = fmaf(nB1, P[1][jt][3], acc[1][jt][3]);
            }
        }
        if (++buf == 3) buf = 0;
    }

    // ---- bias: 2 extra k16 steps; A = norm fragments (bf16), B from g_Bbh
    {
        const ull* bb = g_Bbh + (size_t)sp * 512 + lane;
        #pragma unroll
        for (int kk = 0; kk < 2; ++kk) {
            const int K0 = kk * 16 + 2 * gc;
            uint32_t a00 = bf2(Ns[rA0 * 33 + K0],     Ns[rA0 * 33 + K0 + 1]);
            uint32_t a01 = bf2(Ns[rB0 * 33 + K0],     Ns[rB0 * 33 + K0 + 1]);
            uint32_t a02 = bf2(Ns[rA0 * 33 + K0 + 8], Ns[rA0 * 33 + K0 + 9]);
            uint32_t a03 = bf2(Ns[rB0 * 33 + K0 + 8], Ns[rB0 * 33 + K0 + 9]);
            uint32_t a10 = bf2(Ns[rA1 * 33 + K0],     Ns[rA1 * 33 + K0 + 1]);
            uint32_t a11 = bf2(Ns[rB1 * 33 + K0],     Ns[rB1 * 33 + K0 + 1]);
            uint32_t a12 = bf2(Ns[rA1 * 33 + K0 + 8], Ns[rA1 * 33 + K0 + 9]);
            uint32_t a13 = bf2(Ns[rB1 * 33 + K0 + 8], Ns[rB1 * 33 + K0 + 9]);
            #pragma unroll
            for (int jt = 0; jt < 4; ++jt) {
                ull bv = bb[(kk * 8 + wc * 4 + jt) * 32];
                uint32_t b0, b1;
                u64lohi(bv, b0, b1);
                mma_bf16(acc[0][jt], a00, a01, a02, a03, b0, b1);
                mma_bf16(acc[1][jt], a10, a11, a12, a13, b0, b1);
            }
        }
    }

    float* op = g_partial[sp];
    #pragma unroll
    for (int t = 0; t < 2; ++t) {
        const int ra = nb + (t ? rA1 : rA0);
        const int rbw = nb + (t ? rB1 : rB0);
        #pragma unroll
        for (int jt = 0; jt < 4; ++jt) {
            const int c = (wc * 4 + jt) * 8 + 2 * gc;
            *(float2*)(op + (size_t)ra * O_ + c)  = make_float2(acc[t][jt][0], acc[t][jt][1]);
            *(float2*)(op + (size_t)rbw * O_ + c) = make_float2(acc[t][jt][2], acc[t][jt][3]);
        }
    }
}

// ---------------------------------------------------------------------------
// Kernel 5: softmax, warp per row (pure shfl), 8 rows/block.
// ---------------------------------------------------------------------------
__global__ void __launch_bounds__(256) softmax_kernel(float* __restrict__ out) {
    const int lane = threadIdx.x & 31;
    const int n = blockIdx.x * 8 + (threadIdx.x >> 5);
    const size_t base = (size_t)n * O_;

    float l0 = 0.0f, l1 = 0.0f;
    #pragma unroll
    for (int s = 0; s < 8; ++s) {
        l0 += g_partial[s][base + lane];
        l1 += g_partial[s][base + lane + 32];
    }
    float m = fmaxf(l0, l1);
    #pragma unroll
    for (int o = 16; o > 0; o >>= 1) m = fmaxf(m, __shfl_xor_sync(0xffffffff, m, o));
    float e0 = expf(l0 - m), e1 = expf(l1 - m);
    float s = e0 + e1;
    #pragma unroll
    for (int o = 16; o > 0; o >>= 1) s += __shfl_xor_sync(0xffffffff, s, o);
    float inv = 1.0f / s;
    out[base + lane]      = e0 * inv;
    out[base + lane + 32] = e1 * inv;
}

// ---------------------------------------------------------------------------
extern "C" void kernel_launch(void* const* d_in, const int* in_sizes, int n_in,
                              void* d_out, int out_size) {
    const float* X       = (const float*)d_in[0];
    const float* centers = (const float*)d_in[1];
    const float* sigmas  = (const float*)d_in[2];
    const float* coeffs  = (const float*)d_in[3];
    float* out = (float*)d_out;

    const int SMEM_M = 3 * 32768 + 128 * 33 * (int)sizeof(float);   // 115200 B
    cudaFuncSetAttribute(main_mma_kernel, cudaFuncAttributeMaxDynamicSharedMemorySize, SMEM_M);

    prep_kernel<<<R_, D_>>>(centers, sigmas);                 // 0
    strengths_kernel<<<N_ / 16, 256>>>(X);                    // 1
    prep_bh_kernel<<<R_, 256>>>(coeffs);                      // 2
    main_mma_kernel<<<dim3(N_ / 128, 8), 256, SMEM_M>>>(X);   // 3  <- ncu capture slot
    softmax_kernel<<<N_ / 8, 256>>>(out);                     // 4
}